// round 6
// baseline (speedup 1.0000x reference)
#include <cuda_runtime.h>
#include <cuda_bf16.h>
#include <cstdint>

#define B_ROWS 4096
#define D_IN   1024
#define HID    32768
#define TOPK   32
#define NCAND  48
#define CAP    96

// ---------------- static device scratch ----------------
__device__ uint32_t g_XP[(size_t)B_ROWS * D_IN / 4];   // permuted int8 x (4 MB)
__device__ uint32_t g_WP[(size_t)HID * D_IN / 4];      // permuted int8 W (32 MB)
__device__ float g_sx[B_ROWS], g_isx[B_ROWS];
__device__ float g_sw[HID],   g_isw[HID];
__device__ __align__(16) __nv_bfloat16 g_pre[(size_t)B_ROWS * HID];
__device__ int   g_cand[B_ROWS * CAP];
__device__ int   g_ncand[B_ROWS];
__device__ float g_topv[B_ROWS * TOPK];
__device__ int   g_topi[B_ROWS * TOPK];

__device__ __forceinline__ uint32_t pack_bf16x2(float lo, float hi) {
    uint32_t r;
    asm("cvt.rn.bf16x2.f32 %0, %1, %2;" : "=r"(r) : "f"(hi), "f"(lo));
    return r;
}

// ---------------- row scales ----------------
__global__ __launch_bounds__(256) void k_scaleX(const float* __restrict__ x,
                                                const float* __restrict__ b_dec) {
    const int wid = threadIdx.x >> 5, lane = threadIdx.x & 31;
    const int row = blockIdx.x * 8 + wid;
    float m = 0.f;
    const float* xr = x + (size_t)row * D_IN;
    for (int j = lane; j < D_IN; j += 32) m = fmaxf(m, fabsf(xr[j] - b_dec[j]));
    #pragma unroll
    for (int o = 16; o; o >>= 1) m = fmaxf(m, __shfl_xor_sync(0xffffffffu, m, o));
    if (lane == 0) {
        m = fmaxf(m, 1e-20f);
        g_sx[row]  = 127.f / m;
        g_isx[row] = m * (1.f / 127.f);
    }
}

__global__ __launch_bounds__(256) void k_scaleW(const float* __restrict__ W) {
    const int wid = threadIdx.x >> 5, lane = threadIdx.x & 31;
    const int row = blockIdx.x * 8 + wid;
    float m = 0.f;
    const float* wr = W + (size_t)row * D_IN;
    for (int j = lane; j < D_IN; j += 32) m = fmaxf(m, fabsf(wr[j]));
    #pragma unroll
    for (int o = 16; o; o >>= 1) m = fmaxf(m, __shfl_xor_sync(0xffffffffu, m, o));
    if (lane == 0) {
        m = fmaxf(m, 1e-20f);
        g_sw[row]  = 127.f / m;
        g_isw[row] = m * (1.f / 127.f);
    }
}

__device__ __forceinline__ int q8(float v) {
    int q = __float2int_rn(v);
    return max(-127, min(127, q));
}

// quantize x into fragment-native permuted layout
// XP u32 index = rg*4096 + c*128 + l*4 + r ; rg=row/16, c=k/32
__global__ __launch_bounds__(256) void k_quantX(const float* __restrict__ x,
                                                const float* __restrict__ b_dec) {
    const int rg = blockIdx.x;
    for (int it = 0; it < 16; it++) {
        int w = it * 256 + threadIdx.x;          // 0..4095
        int r = w & 3, l = (w >> 2) & 31, c = w >> 7;
        int r16 = (l >> 2) | ((r & 1) << 3);
        int kkb = ((r >> 1) << 4) | ((l & 3) << 2);
        int row = rg * 16 + r16;
        int k   = c * 32 + kkb;
        float s = g_sx[row];
        const float* xr = x + (size_t)row * D_IN + k;
        const float* bd = b_dec + k;
        uint32_t p = 0;
        #pragma unroll
        for (int j = 0; j < 4; j++) {
            int q = q8((xr[j] - bd[j]) * s);
            p |= (uint32_t)(q & 0xFF) << (8 * j);
        }
        g_XP[(size_t)rg * 4096 + w] = p;
    }
}

// quantize W: WP u32 index = g*2048 + c*64 + l*2 + r ; g=h/8, c=k/32
__global__ __launch_bounds__(256) void k_quantW(const float* __restrict__ W) {
    for (int gi = 0; gi < 4; gi++) {
        int g = blockIdx.x * 4 + gi;
        for (int it = 0; it < 8; it++) {
            int w = it * 256 + threadIdx.x;      // 0..2047
            int r = w & 1, l = (w >> 1) & 31, c = w >> 6;
            int col8 = l >> 2;
            int kkb = (r << 4) | ((l & 3) << 2);
            int h = g * 8 + col8;
            int k = c * 32 + kkb;
            float s = g_sw[h];
            const float* wr = W + (size_t)h * D_IN + k;
            uint32_t p = 0;
            #pragma unroll
            for (int j = 0; j < 4; j++) {
                int q = q8(wr[j] * s);
                p |= (uint32_t)(q & 0xFF) << (8 * j);
            }
            g_WP[(size_t)g * 2048 + w] = p;
        }
    }
}

// ---------------- int8 GEMM: 128x128 tile, BK=64, 3-stage cp.async ----------
#define NCHUNK 16            // K=1024 / 64
#define STG    16384         // A 8KB + B 8KB

__global__ __launch_bounds__(256, 2) void k_gemm_i8(const float* __restrict__ b_enc) {
    __shared__ __align__(16) uint8_t smem[3 * STG];
    const int tid = threadIdx.x, wid = tid >> 5, lane = tid & 31;
    const int bn0 = blockIdx.x * 128, bm0 = blockIdx.y * 128;
    const int warp_m = wid >> 2, warp_n = wid & 3;   // 2 x 4 warps

    const uint8_t* XPb = reinterpret_cast<const uint8_t*>(g_XP) + (size_t)(bm0 >> 4) * 16384;
    const uint8_t* WPb = reinterpret_cast<const uint8_t*>(g_WP) + (size_t)(bn0 >> 3) * 8192;

    int acc[4][4][4];
    #pragma unroll
    for (int a = 0; a < 4; a++)
        #pragma unroll
        for (int b = 0; b < 4; b++)
            #pragma unroll
            for (int c = 0; c < 4; c++) acc[a][b][c] = 0;

    auto loads = [&](int ch, int st) {
        uint8_t* As = smem + st * STG;
        uint8_t* Bs = As + 8192;
        #pragma unroll
        for (int i = 0; i < 2; i++) {
            int idx = i * 256 + tid;             // 0..511 (A 16B chunks)
            int rg_l = idx >> 6, c_l = (idx >> 5) & 1, l = idx & 31;
            uint32_t d = (uint32_t)__cvta_generic_to_shared(As + idx * 16);
            const void* s = XPb + (size_t)rg_l * 16384 + (size_t)(ch * 2 + c_l) * 512 + l * 16;
            asm volatile("cp.async.cg.shared.global [%0], [%1], 16;" :: "r"(d), "l"(s));
        }
        #pragma unroll
        for (int i = 0; i < 2; i++) {
            int idx = i * 256 + tid;             // 0..511 (B 16B chunks)
            int g_l = idx >> 5, c_l = (idx >> 4) & 1, t = idx & 15;
            uint32_t d = (uint32_t)__cvta_generic_to_shared(Bs + idx * 16);
            const void* s = WPb + (size_t)g_l * 8192 + (size_t)(ch * 2 + c_l) * 256 + t * 16;
            asm volatile("cp.async.cg.shared.global [%0], [%1], 16;" :: "r"(d), "l"(s));
        }
        asm volatile("cp.async.commit_group;" ::: "memory");
    };

    loads(0, 0);
    loads(1, 1);

    int stage = 0;
    for (int ch = 0; ch < NCHUNK; ch++) {
        asm volatile("cp.async.wait_group 1;" ::: "memory");
        __syncthreads();
        if (ch + 2 < NCHUNK) loads(ch + 2, (stage + 2) % 3);
        else asm volatile("cp.async.commit_group;" ::: "memory");

        uint8_t* As = smem + stage * STG;
        uint8_t* Bs = As + 8192;
        #pragma unroll
        for (int c = 0; c < 2; c++) {
            uint4 a[4];
            #pragma unroll
            for (int im = 0; im < 4; im++)
                a[im] = *reinterpret_cast<const uint4*>(
                    As + (warp_m * 4 + im) * 1024 + c * 512 + lane * 16);
            uint2 b[4];
            #pragma unroll
            for (int in = 0; in < 4; in++)
                b[in] = *reinterpret_cast<const uint2*>(
                    Bs + (warp_n * 4 + in) * 512 + c * 256 + lane * 8);
            #pragma unroll
            for (int im = 0; im < 4; im++)
                #pragma unroll
                for (int in = 0; in < 4; in++) {
                    int* d = acc[im][in];
                    asm volatile(
                        "mma.sync.aligned.m16n8k32.row.col.s32.s8.s8.s32 "
                        "{%0,%1,%2,%3},{%4,%5,%6,%7},{%8,%9},{%0,%1,%2,%3};"
                        : "+r"(d[0]), "+r"(d[1]), "+r"(d[2]), "+r"(d[3])
                        : "r"(a[im].x), "r"(a[im].y), "r"(a[im].z), "r"(a[im].w),
                          "r"(b[in].x), "r"(b[in].y));
                }
        }
        __syncthreads();
        stage = (stage + 1 == 3) ? 0 : stage + 1;
    }

    // epilogue: rescale + b_enc + relu -> bf16
    #pragma unroll
    for (int im = 0; im < 4; im++) {
        const int row = bm0 + warp_m * 64 + im * 16 + (lane >> 2);
        const float isx0 = g_isx[row], isx8 = g_isx[row + 8];
        #pragma unroll
        for (int in = 0; in < 4; in++) {
            const int col = bn0 + warp_n * 32 + in * 8 + ((lane & 3) << 1);
            const float f0 = g_isw[col], f1 = g_isw[col + 1];
            const float e0 = b_enc[col], e1 = b_enc[col + 1];
            int* d = acc[im][in];
            float v0 = (float)d[0] * isx0 * f0 + e0;
            float v1 = (float)d[1] * isx0 * f1 + e1;
            float v2 = (float)d[2] * isx8 * f0 + e0;
            float v3 = (float)d[3] * isx8 * f1 + e1;
            v0 = fmaxf(v0, 0.f); v1 = fmaxf(v1, 0.f);
            v2 = fmaxf(v2, 0.f); v3 = fmaxf(v3, 0.f);
            *reinterpret_cast<uint32_t*>(&g_pre[(size_t)row * HID + col]) = pack_bf16x2(v0, v1);
            *reinterpret_cast<uint32_t*>(&g_pre[(size_t)(row + 8) * HID + col]) = pack_bf16x2(v2, v3);
        }
    }
}

// ---------------- per-row top-NCAND candidate selection ----------
__global__ __launch_bounds__(256) void k_select() {
    const int row = blockIdx.x;
    const int tid = threadIdx.x, lane = tid & 31;
    const uint4* kp4 = reinterpret_cast<const uint4*>(g_pre + (size_t)row * HID);
    const uint16_t* kp = reinterpret_cast<const uint16_t*>(g_pre + (size_t)row * HID);
    __shared__ int hist[256];
    __shared__ int sB1, sCntGt, sThr, sCnt;

    hist[tid] = 0;
    __syncthreads();
    for (int i = tid; i < HID / 8; i += 256) {
        uint4 u = kp4[i];
        uint32_t ws[4] = {u.x, u.y, u.z, u.w};
        #pragma unroll
        for (int q = 0; q < 4; q++) {
            #pragma unroll
            for (int h = 0; h < 2; h++) {
                uint32_t k = h ? (ws[q] >> 16) : (ws[q] & 0xFFFFu);
                uint32_t b = k >> 8;
                unsigned m = __match_any_sync(0xffffffffu, b);
                if (b && ((m & ((1u << lane) - 1u)) == 0))
                    atomicAdd(&hist[b], __popc(m));
            }
        }
    }
    __syncthreads();
    if (tid == 0) {
        int cum = 0, b;
        for (b = 255; b > 0; b--) {
            if (cum + hist[b] >= NCAND) break;
            cum += hist[b];
        }
        sB1 = b; sCntGt = cum;
    }
    __syncthreads();
    const uint32_t B1 = (uint32_t)sB1;
    const int cntGt = sCntGt;
    hist[tid] = 0;
    __syncthreads();
    for (int i = tid; i < HID / 8; i += 256) {
        uint4 u = kp4[i];
        uint32_t ws[4] = {u.x, u.y, u.z, u.w};
        #pragma unroll
        for (int q = 0; q < 4; q++) {
            #pragma unroll
            for (int h = 0; h < 2; h++) {
                uint32_t k = h ? (ws[q] >> 16) : (ws[q] & 0xFFFFu);
                if ((k >> 8) == B1) atomicAdd(&hist[k & 255u], 1);
            }
        }
    }
    __syncthreads();
    if (tid == 0) {
        int cum = cntGt, l;
        for (l = 255; l > 0; l--) {
            if (cum + hist[l] >= NCAND) break;
            cum += hist[l];
        }
        sThr = (int)((B1 << 8) | (uint32_t)l);
        sCnt = 0;
    }
    __syncthreads();
    const uint16_t thr = (uint16_t)sThr;
    for (int i = tid; i < HID; i += 256) {
        if (kp[i] >= thr) {
            int p = atomicAdd(&sCnt, 1);
            if (p < CAP) g_cand[row * CAP + p] = i;
        }
    }
    __syncthreads();
    if (tid == 0) g_ncand[row] = min(sCnt, CAP);
}

// ---------------- exact recompute (fp32 compensated) + top-32 ---------------
__global__ __launch_bounds__(256) void k_exact(const float* __restrict__ x,
                                               const float* __restrict__ b_dec,
                                               const float* __restrict__ W,
                                               const float* __restrict__ b_enc) {
    const int row = blockIdx.x;
    __shared__ float sae[D_IN];
    __shared__ float vals[CAP];
    __shared__ int   cidx[CAP];
    const int tid = threadIdx.x, lane = tid & 31, wid = tid >> 5;

    for (int i = tid; i < D_IN; i += 256) sae[i] = x[(size_t)row * D_IN + i] - b_dec[i];
    const int nc = g_ncand[row];
    for (int i = tid; i < nc; i += 256) cidx[i] = g_cand[row * CAP + i];
    __syncthreads();

    for (int c = wid; c < nc; c += 8) {
        const int h = cidx[c];
        const float* wr = W + (size_t)h * D_IN;
        float s = 0.f, comp = 0.f;
        for (int j = lane; j < D_IN; j += 32) {
            float p = sae[j] * wr[j];
            float t = s + p;
            comp += (fabsf(s) >= fabsf(p)) ? ((s - t) + p) : ((p - t) + s);
            s = t;
        }
        #pragma unroll
        for (int o = 16; o; o >>= 1) {
            float s2 = __shfl_down_sync(0xffffffffu, s, o);
            float c2 = __shfl_down_sync(0xffffffffu, comp, o);
            float t = s + s2;
            float e = (fabsf(s) >= fabsf(s2)) ? ((s - t) + s2) : ((s2 - t) + s);
            s = t;
            comp = comp + c2 + e;
        }
        if (lane == 0) {
            float v = (s + comp) + b_enc[h];
            vals[c] = (v > 0.f) ? v : 0.f;
        }
    }
    __syncthreads();

    if (wid == 0) {
        for (int t = 0; t < TOPK; t++) {
            float bv = -1.f; int bi = 0x7fffffff; int bc = -1;
            for (int c = lane; c < nc; c += 32) {
                float v = vals[c]; int h = cidx[c];
                if (v > bv || (v == bv && h < bi)) { bv = v; bi = h; bc = c; }
            }
            #pragma unroll
            for (int o = 16; o; o >>= 1) {
                float ov = __shfl_down_sync(0xffffffffu, bv, o);
                int   oi = __shfl_down_sync(0xffffffffu, bi, o);
                int   oc = __shfl_down_sync(0xffffffffu, bc, o);
                if (ov > bv || (ov == bv && oi < bi)) { bv = ov; bi = oi; bc = oc; }
            }
            bv = __shfl_sync(0xffffffffu, bv, 0);
            bi = __shfl_sync(0xffffffffu, bi, 0);
            bc = __shfl_sync(0xffffffffu, bc, 0);
            if (lane == 0) {
                g_topv[row * TOPK + t] = (bc >= 0 && bv > 0.f) ? bv : 0.f;
                g_topi[row * TOPK + t] = (bc >= 0) ? bi : 0;
                if (bc >= 0) vals[bc] = -2.f;
            }
            __syncwarp();
        }
    }
}

// ---------------- decode ----------------
__global__ __launch_bounds__(256) void k_decode(const float* __restrict__ W_dec,
                                                const float* __restrict__ b_dec,
                                                float* __restrict__ out) {
    const int row = blockIdx.x;
    const int tid = threadIdx.x;
    __shared__ float v[TOPK];
    __shared__ int   hi[TOPK];
    if (tid < TOPK) {
        v[tid]  = g_topv[row * TOPK + tid];
        hi[tid] = g_topi[row * TOPK + tid];
    }
    __syncthreads();
    float acc0 = 0.f, acc1 = 0.f, acc2 = 0.f, acc3 = 0.f;
    #pragma unroll 1
    for (int t = 0; t < TOPK; t++) {
        const float* wr = W_dec + (size_t)hi[t] * D_IN;
        const float vt = v[t];
        acc0 += vt * wr[tid];
        acc1 += vt * wr[tid + 256];
        acc2 += vt * wr[tid + 512];
        acc3 += vt * wr[tid + 768];
    }
    float* o = out + (size_t)row * D_IN;
    o[tid]       = acc0 + b_dec[tid];
    o[tid + 256] = acc1 + b_dec[tid + 256];
    o[tid + 512] = acc2 + b_dec[tid + 512];
    o[tid + 768] = acc3 + b_dec[tid + 768];
}

// ---------------- launcher ----------------
extern "C" void kernel_launch(void* const* d_in, const int* in_sizes, int n_in,
                              void* d_out, int out_size) {
    const float* x     = (const float*)d_in[0];
    const float* W_enc = (const float*)d_in[1];
    const float* b_enc = (const float*)d_in[2];
    const float* W_dec = (const float*)d_in[3];
    const float* b_dec = (const float*)d_in[4];
    float* out = (float*)d_out;

    k_scaleX<<<B_ROWS / 8, 256>>>(x, b_dec);
    k_scaleW<<<HID / 8, 256>>>(W_enc);
    k_quantX<<<B_ROWS / 16, 256>>>(x, b_dec);
    k_quantW<<<HID / 8 / 4, 256>>>(W_enc);

    dim3 g(HID / 128, B_ROWS / 128);
    k_gemm_i8<<<g, 256>>>(b_enc);

    k_select<<<B_ROWS, 256>>>();
    k_exact<<<B_ROWS, 256>>>(x, b_dec, W_enc, b_enc);
    k_decode<<<B_ROWS, 256>>>(W_dec, b_dec, out);
}

// round 7
// speedup vs baseline: 1.8501x; 1.8501x over previous
#include <cuda_runtime.h>
#include <cuda_bf16.h>
#include <cstdint>

#define B_ROWS 4096
#define D_IN   1024
#define HID    32768
#define TOPK   32
#define NCAND  48
#define CAP    96

// ---------------- static device scratch ----------------
__device__ __nv_bfloat16 g_Wb[(size_t)HID * D_IN];
__device__ __nv_bfloat16 g_xb[(size_t)B_ROWS * D_IN];
__device__ __align__(16) __nv_bfloat16 g_pre[(size_t)B_ROWS * HID];
__device__ int   g_cand[B_ROWS * CAP];
__device__ int   g_ncand[B_ROWS];
__device__ float g_topv[B_ROWS * TOPK];
__device__ int   g_topi[B_ROWS * TOPK];

// pack two fp32 -> bf16x2 in one SASS cvt (first asm source = upper half)
__device__ __forceinline__ uint32_t pack_bf16x2(float lo, float hi) {
    uint32_t r;
    asm("cvt.rn.bf16x2.f32 %0, %1, %2;" : "=r"(r) : "f"(hi), "f"(lo));
    return r;
}

// ---------------- converters (vectorized) ----------------
__global__ void k_convW(const float* __restrict__ W) {
    size_t n = (size_t)HID * D_IN / 8;
    const float4* src = reinterpret_cast<const float4*>(W);
    uint4* dst = reinterpret_cast<uint4*>(g_Wb);
    for (size_t i = (size_t)blockIdx.x * blockDim.x + threadIdx.x; i < n;
         i += (size_t)gridDim.x * blockDim.x) {
        float4 a = src[2 * i], b = src[2 * i + 1];
        uint4 o;
        o.x = pack_bf16x2(a.x, a.y);
        o.y = pack_bf16x2(a.z, a.w);
        o.z = pack_bf16x2(b.x, b.y);
        o.w = pack_bf16x2(b.z, b.w);
        dst[i] = o;
    }
}

__global__ void k_convX(const float* __restrict__ x, const float* __restrict__ b_dec) {
    size_t n = (size_t)B_ROWS * D_IN;
    for (size_t i = (size_t)blockIdx.x * blockDim.x + threadIdx.x; i < n;
         i += (size_t)gridDim.x * blockDim.x) {
        int d = (int)(i & (D_IN - 1));
        g_xb[i] = __float2bfloat16(x[i] - b_dec[d]);
    }
}

// ---------------- GEMM (known-good round-1 kernel): 128x128, BK=32 ----------
#define BM 128
#define BN 128
#define BK 32
#define KT (D_IN / BK)

__device__ __forceinline__ uint32_t swz32(uint32_t r, uint32_t c) {
    uint32_t pr = r >> 1;
    uint32_t pc = (c + ((r & 1u) << 2)) ^ (pr & 7u);
    return pr * 128u + (pc << 4);
}

__global__ __launch_bounds__(256) void k_gemm(const float* __restrict__ b_enc) {
    __shared__ __align__(16) uint8_t smem[2 * 16384];

    const int tid  = threadIdx.x;
    const int wid  = tid >> 5;
    const int lane = tid & 31;
    const int bm0  = blockIdx.y * BM;
    const int bn0  = blockIdx.x * BN;
    const int warp_m = (wid >> 2) * 64;
    const int warp_n = (wid & 3) * 32;

    float acc[4][4][4];
    #pragma unroll
    for (int a = 0; a < 4; a++)
        #pragma unroll
        for (int b = 0; b < 4; b++)
            #pragma unroll
            for (int c = 0; c < 4; c++) acc[a][b][c] = 0.f;

    auto issueLoads = [&](int kt, int stage) {
        const __nv_bfloat16* Asrc = g_xb + (size_t)bm0 * D_IN + kt * BK;
        const __nv_bfloat16* Bsrc = g_Wb + (size_t)bn0 * D_IN + kt * BK;
        uint8_t* As = smem + stage * 16384;
        uint8_t* Bs = As + 8192;
        #pragma unroll
        for (int i = 0; i < 2; i++) {
            int id = tid + 256 * i;
            int r = id >> 2, c = id & 3;
            uint32_t da = (uint32_t)__cvta_generic_to_shared(As + swz32(r, c));
            const void* sa = Asrc + (size_t)r * D_IN + c * 8;
            asm volatile("cp.async.cg.shared.global [%0], [%1], 16;\n" :: "r"(da), "l"(sa));
            uint32_t db = (uint32_t)__cvta_generic_to_shared(Bs + swz32(r, c));
            const void* sb = Bsrc + (size_t)r * D_IN + c * 8;
            asm volatile("cp.async.cg.shared.global [%0], [%1], 16;\n" :: "r"(db), "l"(sb));
        }
        asm volatile("cp.async.commit_group;\n" ::: "memory");
    };

    auto computeStage = [&](int stage) {
        uint8_t* As = smem + stage * 16384;
        uint8_t* Bs = As + 8192;
        #pragma unroll
        for (int ks = 0; ks < 2; ks++) {
            uint32_t a[4][4], b[2][4];
            #pragma unroll
            for (int im = 0; im < 4; im++) {
                int r = warp_m + im * 16 + (lane & 15);
                int c = ks * 2 + (lane >> 4);
                uint32_t addr = (uint32_t)__cvta_generic_to_shared(As + swz32(r, c));
                asm volatile("ldmatrix.sync.aligned.m8n8.x4.shared.b16 {%0,%1,%2,%3}, [%4];\n"
                             : "=r"(a[im][0]), "=r"(a[im][1]), "=r"(a[im][2]), "=r"(a[im][3])
                             : "r"(addr));
            }
            #pragma unroll
            for (int in2 = 0; in2 < 2; in2++) {
                int r = warp_n + in2 * 16 + (lane & 7) + ((lane & 16) ? 8 : 0);
                int c = ks * 2 + ((lane >> 3) & 1);
                uint32_t addr = (uint32_t)__cvta_generic_to_shared(Bs + swz32(r, c));
                asm volatile("ldmatrix.sync.aligned.m8n8.x4.shared.b16 {%0,%1,%2,%3}, [%4];\n"
                             : "=r"(b[in2][0]), "=r"(b[in2][1]), "=r"(b[in2][2]), "=r"(b[in2][3])
                             : "r"(addr));
            }
            #pragma unroll
            for (int im = 0; im < 4; im++)
                #pragma unroll
                for (int in8 = 0; in8 < 4; in8++) {
                    uint32_t b0 = b[in8 >> 1][(in8 & 1) * 2 + 0];
                    uint32_t b1 = b[in8 >> 1][(in8 & 1) * 2 + 1];
                    float* c4 = acc[im][in8];
                    asm volatile(
                        "mma.sync.aligned.m16n8k16.row.col.f32.bf16.bf16.f32 "
                        "{%0,%1,%2,%3},{%4,%5,%6,%7},{%8,%9},{%0,%1,%2,%3};\n"
                        : "+f"(c4[0]), "+f"(c4[1]), "+f"(c4[2]), "+f"(c4[3])
                        : "r"(a[im][0]), "r"(a[im][1]), "r"(a[im][2]), "r"(a[im][3]),
                          "r"(b0), "r"(b1));
                }
        }
    };

    issueLoads(0, 0);
    for (int kt = 0; kt < KT; kt++) {
        asm volatile("cp.async.wait_group 0;\n" ::: "memory");
        __syncthreads();
        if (kt + 1 < KT) issueLoads(kt + 1, (kt + 1) & 1);
        computeStage(kt & 1);
        __syncthreads();
    }

    const int r0 = bm0 + warp_m + (lane >> 2);
    const int c0 = bn0 + warp_n + (lane & 3) * 2;
    #pragma unroll
    for (int im = 0; im < 4; im++)
        #pragma unroll
        for (int in8 = 0; in8 < 4; in8++) {
            int r = r0 + im * 16;
            int h = c0 + in8 * 8;
            float be0 = b_enc[h], be1 = b_enc[h + 1];
            float v0 = fmaxf(acc[im][in8][0] + be0, 0.f);
            float v1 = fmaxf(acc[im][in8][1] + be1, 0.f);
            float v2 = fmaxf(acc[im][in8][2] + be0, 0.f);
            float v3 = fmaxf(acc[im][in8][3] + be1, 0.f);
            *reinterpret_cast<uint32_t*>(&g_pre[(size_t)r * HID + h]) = pack_bf16x2(v0, v1);
            *reinterpret_cast<uint32_t*>(&g_pre[(size_t)(r + 8) * HID + h]) = pack_bf16x2(v2, v3);
        }
}

// ---------------- per-row top-NCAND candidate selection ----------
__global__ __launch_bounds__(256) void k_select() {
    const int row = blockIdx.x;
    const int tid = threadIdx.x, lane = tid & 31;
    const uint4* kp4 = reinterpret_cast<const uint4*>(g_pre + (size_t)row * HID);
    const uint16_t* kp = reinterpret_cast<const uint16_t*>(g_pre + (size_t)row * HID);
    __shared__ int hist[256];
    __shared__ int sB1, sCntGt, sThr, sCnt;

    hist[tid] = 0;
    __syncthreads();
    for (int i = tid; i < HID / 8; i += 256) {
        uint4 u = kp4[i];
        uint32_t ws[4] = {u.x, u.y, u.z, u.w};
        #pragma unroll
        for (int q = 0; q < 4; q++) {
            #pragma unroll
            for (int h = 0; h < 2; h++) {
                uint32_t k = h ? (ws[q] >> 16) : (ws[q] & 0xFFFFu);
                uint32_t b = k >> 8;
                unsigned m = __match_any_sync(0xffffffffu, b);
                if (b && ((m & ((1u << lane) - 1u)) == 0))
                    atomicAdd(&hist[b], __popc(m));
            }
        }
    }
    __syncthreads();
    if (tid == 0) {
        int cum = 0, b;
        for (b = 255; b > 0; b--) {
            if (cum + hist[b] >= NCAND) break;
            cum += hist[b];
        }
        sB1 = b; sCntGt = cum;
    }
    __syncthreads();
    const uint32_t B1 = (uint32_t)sB1;
    const int cntGt = sCntGt;
    hist[tid] = 0;
    __syncthreads();
    for (int i = tid; i < HID / 8; i += 256) {
        uint4 u = kp4[i];
        uint32_t ws[4] = {u.x, u.y, u.z, u.w};
        #pragma unroll
        for (int q = 0; q < 4; q++) {
            #pragma unroll
            for (int h = 0; h < 2; h++) {
                uint32_t k = h ? (ws[q] >> 16) : (ws[q] & 0xFFFFu);
                if ((k >> 8) == B1) atomicAdd(&hist[k & 255u], 1);
            }
        }
    }
    __syncthreads();
    if (tid == 0) {
        int cum = cntGt, l;
        for (l = 255; l > 0; l--) {
            if (cum + hist[l] >= NCAND) break;
            cum += hist[l];
        }
        sThr = (int)((B1 << 8) | (uint32_t)l);
        sCnt = 0;
    }
    __syncthreads();
    const uint16_t thr = (uint16_t)sThr;
    for (int i = tid; i < HID; i += 256) {
        if (kp[i] >= thr) {
            int p = atomicAdd(&sCnt, 1);
            if (p < CAP) g_cand[row * CAP + p] = i;
        }
    }
    __syncthreads();
    if (tid == 0) g_ncand[row] = min(sCnt, CAP);
}

// ---------------- exact recompute (fp32 compensated) + top-32 ---------------
__global__ __launch_bounds__(256) void k_exact(const float* __restrict__ x,
                                               const float* __restrict__ b_dec,
                                               const float* __restrict__ W,
                                               const float* __restrict__ b_enc) {
    const int row = blockIdx.x;
    __shared__ float sae[D_IN];
    __shared__ float vals[CAP];
    __shared__ int   cidx[CAP];
    const int tid = threadIdx.x, lane = tid & 31, wid = tid >> 5;

    for (int i = tid; i < D_IN; i += 256) sae[i] = x[(size_t)row * D_IN + i] - b_dec[i];
    const int nc = g_ncand[row];
    for (int i = tid; i < nc; i += 256) cidx[i] = g_cand[row * CAP + i];
    __syncthreads();

    for (int c = wid; c < nc; c += 8) {
        const int h = cidx[c];
        const float* wr = W + (size_t)h * D_IN;
        float s = 0.f, comp = 0.f;
        for (int j = lane; j < D_IN; j += 32) {
            float p = sae[j] * wr[j];
            float t = s + p;
            comp += (fabsf(s) >= fabsf(p)) ? ((s - t) + p) : ((p - t) + s);
            s = t;
        }
        #pragma unroll
        for (int o = 16; o; o >>= 1) {
            float s2 = __shfl_down_sync(0xffffffffu, s, o);
            float c2 = __shfl_down_sync(0xffffffffu, comp, o);
            float t = s + s2;
            float e = (fabsf(s) >= fabsf(s2)) ? ((s - t) + s2) : ((s2 - t) + s);
            s = t;
            comp = comp + c2 + e;
        }
        if (lane == 0) {
            float v = (s + comp) + b_enc[h];
            vals[c] = (v > 0.f) ? v : 0.f;
        }
    }
    __syncthreads();

    if (wid == 0) {
        for (int t = 0; t < TOPK; t++) {
            float bv = -1.f; int bi = 0x7fffffff; int bc = -1;
            for (int c = lane; c < nc; c += 32) {
                float v = vals[c]; int h = cidx[c];
                if (v > bv || (v == bv && h < bi)) { bv = v; bi = h; bc = c; }
            }
            #pragma unroll
            for (int o = 16; o; o >>= 1) {
                float ov = __shfl_down_sync(0xffffffffu, bv, o);
                int   oi = __shfl_down_sync(0xffffffffu, bi, o);
                int   oc = __shfl_down_sync(0xffffffffu, bc, o);
                if (ov > bv || (ov == bv && oi < bi)) { bv = ov; bi = oi; bc = oc; }
            }
            bv = __shfl_sync(0xffffffffu, bv, 0);
            bi = __shfl_sync(0xffffffffu, bi, 0);
            bc = __shfl_sync(0xffffffffu, bc, 0);
            if (lane == 0) {
                g_topv[row * TOPK + t] = (bc >= 0 && bv > 0.f) ? bv : 0.f;
                g_topi[row * TOPK + t] = (bc >= 0) ? bi : 0;
                if (bc >= 0) vals[bc] = -2.f;
            }
            __syncwarp();
        }
    }
}

// ---------------- decode ----------------
__global__ __launch_bounds__(256) void k_decode(const float* __restrict__ W_dec,
                                                const float* __restrict__ b_dec,
                                                float* __restrict__ out) {
    const int row = blockIdx.x;
    const int tid = threadIdx.x;
    __shared__ float v[TOPK];
    __shared__ int   hi[TOPK];
    if (tid < TOPK) {
        v[tid]  = g_topv[row * TOPK + tid];
        hi[tid] = g_topi[row * TOPK + tid];
    }
    __syncthreads();
    float acc0 = 0.f, acc1 = 0.f, acc2 = 0.f, acc3 = 0.f;
    #pragma unroll 1
    for (int t = 0; t < TOPK; t++) {
        const float* wr = W_dec + (size_t)hi[t] * D_IN;
        const float vt = v[t];
        acc0 += vt * wr[tid];
        acc1 += vt * wr[tid + 256];
        acc2 += vt * wr[tid + 512];
        acc3 += vt * wr[tid + 768];
    }
    float* o = out + (size_t)row * D_IN;
    o[tid]       = acc0 + b_dec[tid];
    o[tid + 256] = acc1 + b_dec[tid + 256];
    o[tid + 512] = acc2 + b_dec[tid + 512];
    o[tid + 768] = acc3 + b_dec[tid + 768];
}

// ---------------- launcher ----------------
extern "C" void kernel_launch(void* const* d_in, const int* in_sizes, int n_in,
                              void* d_out, int out_size) {
    const float* x     = (const float*)d_in[0];
    const float* W_enc = (const float*)d_in[1];
    const float* b_enc = (const float*)d_in[2];
    const float* W_dec = (const float*)d_in[3];
    const float* b_dec = (const float*)d_in[4];
    float* out = (float*)d_out;

    k_convW<<<2048, 256>>>(W_enc);
    k_convX<<<512, 256>>>(x, b_dec);

    dim3 g(HID / BN, B_ROWS / BM);
    k_gemm<<<g, 256>>>(b_enc);

    k_select<<<B_ROWS, 256>>>();
    k_exact<<<B_ROWS, 256>>>(x, b_dec, W_enc, b_enc);
    k_decode<<<B_ROWS, 256>>>(W_dec, b_dec, out);
}

// round 11
// speedup vs baseline: 2.0187x; 1.0912x over previous
#include <cuda_runtime.h>
#include <cuda_bf16.h>
#include <cstdint>

#define B_ROWS 4096
#define D_IN   1024
#define HID    32768
#define TOPK   32
#define NCAND  48
#define CAP    96

// ---------------- static device scratch ----------------
__device__ __nv_bfloat16 g_Wb[(size_t)HID * D_IN];
__device__ __nv_bfloat16 g_xb[(size_t)B_ROWS * D_IN];
__device__ __align__(16) __nv_bfloat16 g_pre[(size_t)B_ROWS * HID];
__device__ int   g_cand[B_ROWS * CAP];
__device__ int   g_ncand[B_ROWS];
__device__ float g_topv[B_ROWS * TOPK];
__device__ int   g_topi[B_ROWS * TOPK];

__device__ __forceinline__ uint32_t pack_bf16x2(float lo, float hi) {
    uint32_t r;
    asm("cvt.rn.bf16x2.f32 %0, %1, %2;" : "=r"(r) : "f"(hi), "f"(lo));
    return r;
}

// ---------------- converters ----------------
__global__ void k_convW(const float* __restrict__ W) {
    size_t n = (size_t)HID * D_IN / 8;
    const float4* src = reinterpret_cast<const float4*>(W);
    uint4* dst = reinterpret_cast<uint4*>(g_Wb);
    for (size_t i = (size_t)blockIdx.x * blockDim.x + threadIdx.x; i < n;
         i += (size_t)gridDim.x * blockDim.x) {
        float4 a = src[2 * i], b = src[2 * i + 1];
        uint4 o;
        o.x = pack_bf16x2(a.x, a.y);
        o.y = pack_bf16x2(a.z, a.w);
        o.z = pack_bf16x2(b.x, b.y);
        o.w = pack_bf16x2(b.z, b.w);
        dst[i] = o;
    }
}

__global__ void k_convX(const float* __restrict__ x, const float* __restrict__ b_dec) {
    size_t n = (size_t)B_ROWS * D_IN;
    for (size_t i = (size_t)blockIdx.x * blockDim.x + threadIdx.x; i < n;
         i += (size_t)gridDim.x * blockDim.x) {
        int d = (int)(i & (D_IN - 1));
        g_xb[i] = __float2bfloat16(x[i] - b_dec[d]);
    }
}

// ---------------- GEMM: 128x128, BK=32, 3-stage cp.async ----------
#define BM 128
#define BN 128
#define BK 32
#define KT (D_IN / BK)

__device__ __forceinline__ uint32_t swz32(uint32_t r, uint32_t c) {
    uint32_t pr = r >> 1;
    uint32_t pc = (c + ((r & 1u) << 2)) ^ (pr & 7u);
    return pr * 128u + (pc << 4);
}

__global__ __launch_bounds__(256) void k_gemm(const float* __restrict__ b_enc) {
    __shared__ __align__(16) uint8_t smem[3 * 16384];   // 48 KB

    const int tid  = threadIdx.x;
    const int wid  = tid >> 5;
    const int lane = tid & 31;
    const int bm0  = blockIdx.y * BM;
    const int bn0  = blockIdx.x * BN;
    const int warp_m = (wid >> 2) * 64;
    const int warp_n = (wid & 3) * 32;

    float acc[4][4][4];
    #pragma unroll
    for (int a = 0; a < 4; a++)
        #pragma unroll
        for (int b = 0; b < 4; b++)
            #pragma unroll
            for (int c = 0; c < 4; c++) acc[a][b][c] = 0.f;

    auto issueLoads = [&](int kt, int stage) {
        const __nv_bfloat16* Asrc = g_xb + (size_t)bm0 * D_IN + kt * BK;
        const __nv_bfloat16* Bsrc = g_Wb + (size_t)bn0 * D_IN + kt * BK;
        uint8_t* As = smem + stage * 16384;
        uint8_t* Bs = As + 8192;
        #pragma unroll
        for (int i = 0; i < 2; i++) {
            int id = tid + 256 * i;
            int r = id >> 2, c = id & 3;
            uint32_t da = (uint32_t)__cvta_generic_to_shared(As + swz32(r, c));
            const void* sa = Asrc + (size_t)r * D_IN + c * 8;
            asm volatile("cp.async.cg.shared.global [%0], [%1], 16;\n" :: "r"(da), "l"(sa));
            uint32_t db = (uint32_t)__cvta_generic_to_shared(Bs + swz32(r, c));
            const void* sb = Bsrc + (size_t)r * D_IN + c * 8;
            asm volatile("cp.async.cg.shared.global [%0], [%1], 16;\n" :: "r"(db), "l"(sb));
        }
    };

    auto computeStage = [&](int stage) {
        uint8_t* As = smem + stage * 16384;
        uint8_t* Bs = As + 8192;
        #pragma unroll
        for (int ks = 0; ks < 2; ks++) {
            uint32_t a[4][4], b[2][4];
            #pragma unroll
            for (int im = 0; im < 4; im++) {
                int r = warp_m + im * 16 + (lane & 15);
                int c = ks * 2 + (lane >> 4);
                uint32_t addr = (uint32_t)__cvta_generic_to_shared(As + swz32(r, c));
                asm volatile("ldmatrix.sync.aligned.m8n8.x4.shared.b16 {%0,%1,%2,%3}, [%4];\n"
                             : "=r"(a[im][0]), "=r"(a[im][1]), "=r"(a[im][2]), "=r"(a[im][3])
                             : "r"(addr));
            }
            #pragma unroll
            for (int in2 = 0; in2 < 2; in2++) {
                int r = warp_n + in2 * 16 + (lane & 7) + ((lane & 16) ? 8 : 0);
                int c = ks * 2 + ((lane >> 3) & 1);
                uint32_t addr = (uint32_t)__cvta_generic_to_shared(Bs + swz32(r, c));
                asm volatile("ldmatrix.sync.aligned.m8n8.x4.shared.b16 {%0,%1,%2,%3}, [%4];\n"
                             : "=r"(b[in2][0]), "=r"(b[in2][1]), "=r"(b[in2][2]), "=r"(b[in2][3])
                             : "r"(addr));
            }
            #pragma unroll
            for (int im = 0; im < 4; im++)
                #pragma unroll
                for (int in8 = 0; in8 < 4; in8++) {
                    uint32_t b0 = b[in8 >> 1][(in8 & 1) * 2 + 0];
                    uint32_t b1 = b[in8 >> 1][(in8 & 1) * 2 + 1];
                    float* c4 = acc[im][in8];
                    asm volatile(
                        "mma.sync.aligned.m16n8k16.row.col.f32.bf16.bf16.f32 "
                        "{%0,%1,%2,%3},{%4,%5,%6,%7},{%8,%9},{%0,%1,%2,%3};\n"
                        : "+f"(c4[0]), "+f"(c4[1]), "+f"(c4[2]), "+f"(c4[3])
                        : "r"(a[im][0]), "r"(a[im][1]), "r"(a[im][2]), "r"(a[im][3]),
                          "r"(b0), "r"(b1));
                }
        }
    };

    issueLoads(0, 0);
    asm volatile("cp.async.commit_group;\n" ::: "memory");
    issueLoads(1, 1);
    asm volatile("cp.async.commit_group;\n" ::: "memory");

    for (int kt = 0; kt < KT; kt++) {
        asm volatile("cp.async.wait_group 1;\n" ::: "memory");
        __syncthreads();
        if (kt + 2 < KT) issueLoads(kt + 2, (kt + 2) % 3);
        asm volatile("cp.async.commit_group;\n" ::: "memory");
        computeStage(kt % 3);
    }

    const int r0 = bm0 + warp_m + (lane >> 2);
    const int c0 = bn0 + warp_n + (lane & 3) * 2;
    #pragma unroll
    for (int im = 0; im < 4; im++)
        #pragma unroll
        for (int in8 = 0; in8 < 4; in8++) {
            int r = r0 + im * 16;
            int h = c0 + in8 * 8;
            float be0 = b_enc[h], be1 = b_enc[h + 1];
            float v0 = fmaxf(acc[im][in8][0] + be0, 0.f);
            float v1 = fmaxf(acc[im][in8][1] + be1, 0.f);
            float v2 = fmaxf(acc[im][in8][2] + be0, 0.f);
            float v3 = fmaxf(acc[im][in8][3] + be1, 0.f);
            *reinterpret_cast<uint32_t*>(&g_pre[(size_t)r * HID + h]) = pack_bf16x2(v0, v1);
            *reinterpret_cast<uint32_t*>(&g_pre[(size_t)(r + 8) * HID + h]) = pack_bf16x2(v2, v3);
        }
}

// ------- top-NCAND selection: 12-bit hist + exact 16-bit refinement --------
__global__ __launch_bounds__(256) void k_select() {
    const int row = blockIdx.x;
    const int tid = threadIdx.x, lane = tid & 31, wi = tid >> 5;
    const uint4* kp4 = reinterpret_cast<const uint4*>(g_pre + (size_t)row * HID);
    __shared__ int hist[4096];
    __shared__ int sub[16];
    __shared__ int warpsum[8];
    __shared__ int sB1, sAbove, sThr, sCnt;

    #pragma unroll
    for (int i = 0; i < 16; i++) hist[tid + 256 * i] = 0;
    if (tid < 16) sub[tid] = 0;
    if (tid == 0) { sB1 = -1; sAbove = 0; sThr = 1; sCnt = 0; }
    __syncthreads();

    // pass 1: 12-bit histogram, skip zeros
    for (int i = tid; i < HID / 8; i += 256) {
        uint4 u = kp4[i];
        uint32_t ws[4] = {u.x, u.y, u.z, u.w};
        #pragma unroll
        for (int q = 0; q < 4; q++) {
            uint32_t k0 = ws[q] & 0xFFFFu, k1 = ws[q] >> 16;
            if (k0) atomicAdd(&hist[k0 >> 4], 1);
            if (k1) atomicAdd(&hist[k1 >> 4], 1);
        }
    }
    __syncthreads();

    // descending suffix scan to find coarse bucket
    const int base = 4095 - tid * 16;
    int s = 0;
    #pragma unroll
    for (int j = 0; j < 16; j++) s += hist[base - j];
    int inc = s;
    #pragma unroll
    for (int o = 1; o < 32; o <<= 1) {
        int v = __shfl_up_sync(0xffffffffu, inc, o);
        if (lane >= o) inc += v;
    }
    if (lane == 31) warpsum[wi] = inc;
    __syncthreads();
    if (wi == 0) {
        int wsv = (lane < 8) ? warpsum[lane] : 0;
        #pragma unroll
        for (int o = 1; o < 8; o <<= 1) {
            int v = __shfl_up_sync(0xffffffffu, wsv, o);
            if (lane >= o) wsv += v;
        }
        if (lane < 8) warpsum[lane] = wsv;
    }
    __syncthreads();
    const int above0 = inc - s + (wi ? warpsum[wi - 1] : 0);
    if (above0 < NCAND && above0 + s >= NCAND) {
        int cum = above0;
        #pragma unroll
        for (int j = 0; j < 16; j++) {
            int b = base - j;
            int hb = hist[b];
            if (cum + hb >= NCAND) { sB1 = b; sAbove = cum; break; }
            cum += hb;
        }
    }
    __syncthreads();
    const int B1 = sB1;

    // pass 2: 16-way sub-histogram inside coarse bucket
    if (B1 >= 0) {
        for (int i = tid; i < HID / 8; i += 256) {
            uint4 u = kp4[i];
            uint32_t ws[4] = {u.x, u.y, u.z, u.w};
            #pragma unroll
            for (int q = 0; q < 4; q++) {
                uint32_t k0 = ws[q] & 0xFFFFu, k1 = ws[q] >> 16;
                if ((int)(k0 >> 4) == B1) atomicAdd(&sub[k0 & 15u], 1);
                if ((int)(k1 >> 4) == B1) atomicAdd(&sub[k1 & 15u], 1);
            }
        }
    }
    __syncthreads();
    if (tid == 0 && B1 >= 0) {
        int cum = sAbove;
        for (int c2 = 15; c2 >= 0; c2--) {
            cum += sub[c2];
            if (cum >= NCAND) { sThr = (B1 << 4) | c2; break; }
        }
    }
    __syncthreads();
    const uint32_t thr = (uint32_t)sThr;   // >= 1, so zeros excluded

    // pass 3: collect candidate indices
    for (int i = tid; i < HID / 8; i += 256) {
        uint4 u = kp4[i];
        uint32_t ws[4] = {u.x, u.y, u.z, u.w};
        #pragma unroll
        for (int q = 0; q < 4; q++) {
            #pragma unroll
            for (int h = 0; h < 2; h++) {
                uint32_t k = h ? (ws[q] >> 16) : (ws[q] & 0xFFFFu);
                if (k >= thr) {
                    int p = atomicAdd(&sCnt, 1);
                    if (p < CAP) g_cand[row * CAP + p] = i * 8 + q * 2 + h;
                }
            }
        }
    }
    __syncthreads();
    if (tid == 0) g_ncand[row] = min(sCnt, CAP);
}

// ---------------- exact recompute (fp32 compensated) + top-32 ---------------
__global__ __launch_bounds__(256) void k_exact(const float* __restrict__ x,
                                               const float* __restrict__ b_dec,
                                               const float* __restrict__ W,
                                               const float* __restrict__ b_enc) {
    const int row = blockIdx.x;
    __shared__ float sae[D_IN];
    __shared__ float vals[CAP];
    __shared__ int   cidx[CAP];
    const int tid = threadIdx.x, lane = tid & 31, wid = tid >> 5;

    for (int i = tid; i < D_IN; i += 256) sae[i] = x[(size_t)row * D_IN + i] - b_dec[i];
    const int nc = g_ncand[row];
    for (int i = tid; i < nc; i += 256) cidx[i] = g_cand[row * CAP + i];
    __syncthreads();

    for (int c = wid; c < nc; c += 8) {
        const int h = cidx[c];
        const float* wr = W + (size_t)h * D_IN;
        float s = 0.f, comp = 0.f;
        for (int j = lane; j < D_IN; j += 32) {
            float p = sae[j] * wr[j];
            float t = s + p;
            comp += (fabsf(s) >= fabsf(p)) ? ((s - t) + p) : ((p - t) + s);
            s = t;
        }
        #pragma unroll
        for (int o = 16; o; o >>= 1) {
            float s2 = __shfl_down_sync(0xffffffffu, s, o);
            float c2 = __shfl_down_sync(0xffffffffu, comp, o);
            float t = s + s2;
            float e = (fabsf(s) >= fabsf(s2)) ? ((s - t) + s2) : ((s2 - t) + s);
            s = t;
            comp = comp + c2 + e;
        }
        if (lane == 0) {
            float v = (s + comp) + b_enc[h];
            vals[c] = (v > 0.f) ? v : 0.f;
        }
    }
    __syncthreads();

    if (wid == 0) {
        for (int t = 0; t < TOPK; t++) {
            float bv = -1.f; int bi = 0x7fffffff; int bc = -1;
            for (int c = lane; c < nc; c += 32) {
                float v = vals[c]; int h = cidx[c];
                if (v > bv || (v == bv && h < bi)) { bv = v; bi = h; bc = c; }
            }
            #pragma unroll
            for (int o = 16; o; o >>= 1) {
                float ov = __shfl_down_sync(0xffffffffu, bv, o);
                int   oi = __shfl_down_sync(0xffffffffu, bi, o);
                int   oc = __shfl_down_sync(0xffffffffu, bc, o);
                if (ov > bv || (ov == bv && oi < bi)) { bv = ov; bi = oi; bc = oc; }
            }
            bv = __shfl_sync(0xffffffffu, bv, 0);
            bi = __shfl_sync(0xffffffffu, bi, 0);
            bc = __shfl_sync(0xffffffffu, bc, 0);
            if (lane == 0) {
                g_topv[row * TOPK + t] = (bc >= 0 && bv > 0.f) ? bv : 0.f;
                g_topi[row * TOPK + t] = (bc >= 0) ? bi : 0;
                if (bc >= 0) vals[bc] = -2.f;
            }
            __syncwarp();
        }
    }
}

// ---------------- decode ----------------
__global__ __launch_bounds__(256) void k_decode(const float* __restrict__ W_dec,
                                                const float* __restrict__ b_dec,
                                                float* __restrict__ out) {
    const int row = blockIdx.x;
    const int tid = threadIdx.x;
    __shared__ float v[TOPK];
    __shared__ int   hi[TOPK];
    if (tid < TOPK) {
        v[tid]  = g_topv[row * TOPK + tid];
        hi[tid] = g_topi[row * TOPK + tid];
    }
    __syncthreads();
    float acc0 = 0.f, acc1 = 0.f, acc2 = 0.f, acc3 = 0.f;
    #pragma unroll 1
    for (int t = 0; t < TOPK; t++) {
        const float* wr = W_dec + (size_t)hi[t] * D_IN;
        const float vt = v[t];
        acc0 += vt * wr[tid];
        acc1 += vt * wr[tid + 256];
        acc2 += vt * wr[tid + 512];
        acc3 += vt * wr[tid + 768];
    }
    float* o = out + (size_t)row * D_IN;
    o[tid]       = acc0 + b_dec[tid];
    o[tid + 256] = acc1 + b_dec[tid + 256];
    o[tid + 512] = acc2 + b_dec[tid + 512];
    o[tid + 768] = acc3 + b_dec[tid + 768];
}

// ---------------- launcher ----------------
extern "C" void kernel_launch(void* const* d_in, const int* in_sizes, int n_in,
                              void* d_out, int out_size) {
    const float* x     = (const float*)d_in[0];
    const float* W_enc = (const float*)d_in[1];
    const float* b_enc = (const float*)d_in[2];
    const float* W_dec = (const float*)d_in[3];
    const float* b_dec = (const float*)d_in[4];
    float* out = (float*)d_out;

    k_convW<<<2048, 256>>>(W_enc);
    k_convX<<<512, 256>>>(x, b_dec);

    dim3 g(HID / BN, B_ROWS / BM);
    k_gemm<<<g, 256>>>(b_enc);

    k_select<<<B_ROWS, 256>>>();
    k_exact<<<B_ROWS, 256>>>(x, b_dec, W_enc, b_enc);
    k_decode<<<B_ROWS, 256>>>(W_dec, b_dec, out);
}